// round 7
// baseline (speedup 1.0000x reference)
#include <cuda_runtime.h>
#include <cuda_bf16.h>
#include <math.h>
#include <stdint.h>

#define NROWS 4096
#define DIM 512
#define NSPLIT 14

// ---------------- descriptors ----------------
struct ERole { int enabled; int src; int e; int op; float w; };
struct GemmDesc {
  int enabled, nterms, mul;
  int srcA[3];
  int wKind[3], wIdx[3];
  int bKind, bIdx;
  int actCode;          // 0 none, 1 relu, 2 gelu
  int resBuf, dstBuf;
  float scale;
};

__device__ ERole    g_erole[8][3];
__device__ GemmDesc g_gd[8][7];
__device__ int      g_node_act[8];
__device__ float    g_node_aw[8];
__device__ int      g_rem_mask;

// ---------------- buffers ----------------
__device__ float g_outbuf[8][NROWS*DIM];   // node outputs (fp32)
__device__ float g_qkv[3][NROWS*DIM];      // q,k,v edge outputs (fp32)
__device__ float g_tt[3][NROWS*DIM];       // node projection temps (fp32)

// split bf16 hi/lo companions for every GEMM-A-capable buffer.
// slot map: 0,1 = inpute,inputo; 2-4 = qkv; 5-7 = prep; 8-10 = tt; 11 = lnq; 12 = attn; 13 = mul product
__device__ __nv_bfloat16 g_sph[NSPLIT][NROWS*DIM];
__device__ __nv_bfloat16 g_spl[NSPLIT][NROWS*DIM];

// transposed bf16 weights: [w][n*512+k], hi and lo. w: 0..33 edge, 34..65 node
__device__ __nv_bfloat16 g_Wth[66u*262144u];
__device__ __nv_bfloat16 g_Wtl[66u*262144u];

// buffer id map: 0 inpute, 1 inputo, 2..9 outbuf, 10..12 qkv, 13..15 prep, 16..18 tt, 19 lnq, 20 attn, 21 mulprod
__device__ __forceinline__ int slotOf(int id){
  if(id<2) return id;
  if(id>=10) return id-8;
  return -1;
}
__device__ __forceinline__ const float* bufPtrC(int id, const float* inpute, const float* inputo){
  if(id==0) return inpute;
  if(id==1) return inputo;
  if(id<10) return g_outbuf[id-2];
  if(id<13) return g_qkv[id-10];
  return g_tt[id-16];   // 16..18 (only fp32-backed ids are used here)
}
__device__ __forceinline__ float* bufPtrM(int id){
  if(id<10) return g_outbuf[id-2];
  if(id<13) return g_qkv[id-10];
  return g_tt[id-16];
}

__device__ __forceinline__ float geluf(float x){
  float inner = 0.7978845608028654f*(x + 0.044715f*x*x*x);
  return 0.5f*x*(1.f+tanhf(inner));
}
__device__ __forceinline__ float sigmoidf(float x){ return 1.f/(1.f+expf(-x)); }

__device__ __forceinline__ void store_split2(__nv_bfloat16* ph, __nv_bfloat16* pl, size_t off,
                                             float v0, float v1){
  __nv_bfloat16 h0=__float2bfloat16(v0); float r0=v0-__bfloat162float(h0);
  __nv_bfloat16 h1=__float2bfloat16(v1); float r1=v1-__bfloat162float(h1);
  __nv_bfloat162 hh; hh.x=h0; hh.y=h1; *(__nv_bfloat162*)(ph+off)=hh;
  __nv_bfloat162 ll; ll.x=__float2bfloat16(r0); ll.y=__float2bfloat16(r1); *(__nv_bfloat162*)(pl+off)=ll;
}

__device__ __forceinline__ float blockReduceSum(float v){
  __shared__ float red[32];
  int lane = threadIdx.x & 31, w = threadIdx.x >> 5;
  #pragma unroll
  for(int o=16;o;o>>=1) v += __shfl_xor_sync(0xffffffffu, v, o);
  if(lane==0) red[w]=v;
  __syncthreads();
  if(w==0){
    float x = (lane < (int)(blockDim.x>>5)) ? red[lane] : 0.f;
    #pragma unroll
    for(int o=16;o;o>>=1) x += __shfl_xor_sync(0xffffffffu, x, o);
    if(lane==0) red[0]=x;
  }
  __syncthreads();
  float r = red[0];
  __syncthreads();
  return r;
}

// ---------------- routing ----------------
__device__ void selrange(const float* p, int lo, int hi, int& sel, float& w){
  int bi=lo; float bv=p[lo];
  for(int i=lo+1;i<hi;i++) if(p[i]>bv){bv=p[i];bi=i;}
  float s=0.f;
  for(int i=lo;i<hi;i++) s += expf(p[i]-bv);
  sel=bi; w=1.f/s;
}

__device__ void fillRole(int c,int role,int sel,float w,int lind,int snode,int& processed,int computeEnabled){
  int se = sel/5, op = sel%5;
  int inn = (se==0)? -2 : snode+se;
  if(inn>=0) processed |= (1<<inn);
  int src = (inn==-2)?0 : ((inn==-1)?1 : (2+inn));
  ERole er; er.enabled=computeEnabled; er.src=src; er.e=lind+se; er.op=op; er.w=w;
  g_erole[c][role]=er;
}

__device__ void setGemm(int c,int slot,int src0,int wKind0,int wIdx0,int bKind,int bIdx,
                        int actCode,int resBuf,int dstBuf,float scale){
  GemmDesc gd;
  gd.enabled=1; gd.nterms=1; gd.mul=0;
  gd.srcA[0]=src0; gd.srcA[1]=src0; gd.srcA[2]=src0;
  gd.wKind[0]=wKind0; gd.wIdx[0]=wIdx0;
  gd.wKind[1]=wKind0; gd.wIdx[1]=wIdx0; gd.wKind[2]=wKind0; gd.wIdx[2]=wIdx0;
  gd.bKind=bKind; gd.bIdx=bIdx;
  gd.actCode=actCode; gd.resBuf=resBuf; gd.dstBuf=dstBuf; gd.scale=scale;
  g_gd[c][slot]=gd;
}

__global__ void route_kernel(const float* __restrict__ node_p, const float* __restrict__ edge_p){
  if(threadIdx.x!=0 || blockIdx.x!=0) return;
  int processed = 0;
  int lind = 0;
  for(int c=0;c<8;c++){
    for(int s=0;s<7;s++) g_gd[c][s].enabled=0;
    for(int r=0;r<3;r++) g_erole[c][r].enabled=0;

    int nsrc = (c+2<5)? c+2 : 5;
    int snode = c - nsrc;
    int L = nsrc*5;
    const float* ep0 = edge_p + lind*5;
    const float* ep1 = edge_p + 170 + lind*5;
    const float* ep2 = edge_p + 340 + lind*5;
    const float* np  = node_p + c*8;

    int act=0; { float b=np[0]; for(int i=1;i<8;i++) if(np[i]>b){b=np[i];act=i;} }
    float aw;
    { float m=np[0]; for(int i=1;i<8;i++) m=fmaxf(m,np[i]);
      float s=0.f; for(int i=0;i<8;i++) s+=expf(np[i]-m);
      aw = expf(np[act]-m)/s; }
    g_node_act[c]=act; g_node_aw[c]=aw;

    int qsel; float qw;
    selrange(ep0, 5, L, qsel, qw);
    fillRole(c,0,qsel,qw,lind,snode,processed,1);

    int ksel = -1;
    if(act<7){
      int lo = (act>0)?5:0;
      float kw;
      selrange(ep1, lo, L, ksel, kw);
      fillRole(c,1,ksel,kw,lind,snode,processed,1);
    }
    if(act<5){
      int vsel; float vw;
      if(act==0 && (ksel/5)==0){
        selrange(ep2, 0, 5, vsel, vw);
      } else {
        int lo = (act>0)?5:0;
        selrange(ep2, lo, L, vsel, vw);
      }
      fillRole(c,2,vsel,vw,lind,snode,processed,(act!=1)?1:0);
    }

    for(int r2=0;r2<3;r2++){
      ERole er = g_erole[c][r2];
      if(er.enabled && er.op!=4){
        int ac = (er.op==0)?1:((er.op==1)?2:0);
        setGemm(c, r2, 13+r2, 0, er.e, 0, er.e, ac, -1, 10+r2, er.w);
      }
    }

    int cw = c*4;
    if(act==0){
      setGemm(c,3,19,1,cw+0,1,cw+0,0,-1,16,1.f);   // qh = LN(q)@W0+b0
      setGemm(c,4,11,1,cw+1,1,cw+1,0,-1,17,1.f);   // kh
      setGemm(c,5,12,1,cw+2,1,cw+2,0,-1,18,1.f);   // vh
      setGemm(c,6,20,1,cw+3,1,cw+3,0,10,2+c,aw);   // out
    } else if(act==1){
      setGemm(c,3,10,1,cw+0,1,cw+0,2,-1,16,1.f);   // t0 = gelu(q@W0+b0)
      setGemm(c,4,11,1,cw+1,1,cw+1,0,-1,17,1.f);   // t1 = k@W1+b1
      setGemm(c,6,21,1,cw+3,1,cw+3,0,10,2+c,aw);   // out = aw*(q + (t0*t1)@W3+b3), product pre-split (id 21)
    } else if(act==3){
      setGemm(c,3,10,1,cw+0,-1,0,1,-1,16,1.f);     // t0 = relu(q@W0+k@W1+v@W2)
      g_gd[c][3].nterms=3;
      g_gd[c][3].srcA[1]=11; g_gd[c][3].srcA[2]=12;
      g_gd[c][3].wKind[1]=1; g_gd[c][3].wIdx[1]=cw+1;
      g_gd[c][3].wKind[2]=1; g_gd[c][3].wIdx[2]=cw+2;
      setGemm(c,6,16,1,cw+3,1,cw+3,0,10,2+c,aw);
    } else if(act==5){
      setGemm(c,3,11,1,cw+1,1,cw+1,2,-1,16,1.f);
    }

    lind += nsrc;
  }
  g_rem_mask = (~processed) & 0xFF;
}

// ---------------- input conversion: fp32 -> bf16 hi/lo (slots 0,1) ----------------
__global__ void convin_kernel(const float* __restrict__ A, const float* __restrict__ B){
  const float* src = blockIdx.y ? B : A;
  int slot = blockIdx.y;
  size_t i4 = ((size_t)blockIdx.x*256 + threadIdx.x)*4;
  float4 v = *(const float4*)(src + i4);
  store_split2(g_sph[slot], g_spl[slot], i4,   v.x, v.y);
  store_split2(g_sph[slot], g_spl[slot], i4+2, v.z, v.w);
}

// ---------------- weight conversion: fp32 [k][n] -> bf16 hi/lo transposed [n][k] ----------------
__global__ void convw_kernel(const float* __restrict__ eW, const float* __restrict__ nW){
  __shared__ float tile[32][33];
  int w = blockIdx.z;
  const float* src = (w<34) ? eW + (size_t)w*262144 : nW + (size_t)(w-34)*262144;
  int k0 = blockIdx.x*32, n0 = blockIdx.y*32;
  int tr = threadIdx.x>>3;
  int tc = (threadIdx.x&7)*4;
  float4 v = *(const float4*)(src + (size_t)(k0+tr)*512 + n0+tc);
  tile[tr][tc+0]=v.x; tile[tr][tc+1]=v.y; tile[tr][tc+2]=v.z; tile[tr][tc+3]=v.w;
  __syncthreads();
  int nr = threadIdx.x>>3;
  int kc = (threadIdx.x&7)*4;
  union { __nv_bfloat16 b[4]; uint2 u; } ph, pl;
  #pragma unroll
  for(int j=0;j<4;j++){
    float x = tile[kc+j][nr];
    __nv_bfloat16 h = __float2bfloat16(x);
    ph.b[j] = h;
    pl.b[j] = __float2bfloat16(x - __bfloat162float(h));
  }
  size_t off = (size_t)w*262144 + (size_t)(n0+nr)*512 + k0+kc;
  *(uint2*)(g_Wth + off) = ph.u;
  *(uint2*)(g_Wtl + off) = pl.u;
}

// ---------------- edge prep: LN / copy / identity -> split bf16 ----------------
__global__ void prep_kernel(int c, const float* __restrict__ inpute, const float* __restrict__ inputo,
                            const float* __restrict__ edge_g, const float* __restrict__ edge_beta){
  int role = blockIdx.z;
  ERole er = g_erole[c][role];
  if(!er.enabled) return;
  int row = blockIdx.x;
  int t2 = threadIdx.x*2;
  size_t off = (size_t)row*DIM + t2;
  const float* x = bufPtrC(er.src, inpute, inputo);
  float a = x[off], b = x[off+1];
  if(er.op==4){
    float v0 = er.w*a, v1 = er.w*b;
    *(float2*)(g_qkv[role]+off) = make_float2(v0,v1);
    store_split2(g_sph[2+role], g_spl[2+role], off, v0, v1);
    return;
  }
  if(er.op==3){
    store_split2(g_sph[5+role], g_spl[5+role], off, a, b);
    return;
  }
  float s  = blockReduceSum(a+b);
  float mean = s*(1.f/512.f);
  float da=a-mean, db=b-mean;
  float s2 = blockReduceSum(da*da+db*db);
  float rstd = rsqrtf(s2*(1.f/512.f)+1e-6f);
  const float* g  = edge_g    + (size_t)er.e*DIM;
  const float* be = edge_beta + (size_t)er.e*DIM;
  store_split2(g_sph[5+role], g_spl[5+role], off,
               da*rstd*g[t2]+be[t2], db*rstd*g[t2+1]+be[t2+1]);
}

// ---------------- LN(q) for MHA -> split slot 11 ----------------
__global__ void lnq_kernel(int c, const float* __restrict__ node_g, const float* __restrict__ node_beta){
  if(g_node_act[c]!=0) return;
  int row=blockIdx.x, t2=threadIdx.x*2;
  size_t off=(size_t)row*DIM + t2;
  float a=g_qkv[0][off], b=g_qkv[0][off+1];
  float s = blockReduceSum(a+b);
  float mean = s*(1.f/512.f);
  float da=a-mean, db=b-mean;
  float s2 = blockReduceSum(da*da+db*db);
  float rstd = rsqrtf(s2*(1.f/512.f)+1e-6f);
  const float* g  = node_g    + (size_t)c*DIM;
  const float* be = node_beta + (size_t)c*DIM;
  store_split2(g_sph[11], g_spl[11], off,
               da*rstd*g[t2]+be[t2], db*rstd*g[t2+1]+be[t2+1]);
}

// ---------------- mul product (act==1): tt0*tt1 -> split slot 13 ----------------
__global__ void mul_kernel(int c){
  if(g_node_act[c]!=1) return;
  size_t off=(size_t)blockIdx.x*DIM + threadIdx.x*2;
  float2 a=*(const float2*)(g_tt[0]+off);
  float2 b=*(const float2*)(g_tt[1]+off);
  store_split2(g_sph[13], g_spl[13], off, a.x*b.x, a.y*b.y);
}

// ---------------- tensor-core GEMM: cp.async + ldmatrix + 2 CTA/SM ----------------
#define SROW 40
#define PART (128*SROW)     // 5120 elems
#define STAGE (4*PART)      // elems per stage

__device__ __forceinline__ void cpa16(uint32_t sdst, const void* gsrc){
  asm volatile("cp.async.cg.shared.global [%0], [%1], 16;\n" :: "r"(sdst), "l"(gsrc));
}
#define CP_COMMIT asm volatile("cp.async.commit_group;\n"::)
#define CP_WAIT(N) asm volatile("cp.async.wait_group %0;\n" :: "n"(N))

__device__ __forceinline__ void ldsm4(uint32_t& r0,uint32_t& r1,uint32_t& r2,uint32_t& r3, uint32_t saddr){
  asm volatile("ldmatrix.sync.aligned.m8n8.x4.shared.b16 {%0,%1,%2,%3}, [%4];"
    : "=r"(r0),"=r"(r1),"=r"(r2),"=r"(r3) : "r"(saddr));
}
__device__ __forceinline__ void mma16816(float* c, uint32_t a0,uint32_t a1,uint32_t a2,uint32_t a3,
                                         uint32_t b0, uint32_t b1){
  asm volatile("mma.sync.aligned.m16n8k16.row.col.f32.bf16.bf16.f32 "
    "{%0,%1,%2,%3}, {%4,%5,%6,%7}, {%8,%9}, {%0,%1,%2,%3};"
    : "+f"(c[0]),"+f"(c[1]),"+f"(c[2]),"+f"(c[3])
    : "r"(a0),"r"(a1),"r"(a2),"r"(a3),"r"(b0),"r"(b1));
}

__global__ void __launch_bounds__(256,2) gemm_kernel(int c,int slotBase,
  const float* __restrict__ inpute,const float* __restrict__ inputo,
  const float* __restrict__ edge_b,const float* __restrict__ node_b)
{
  GemmDesc gd = g_gd[c][slotBase + blockIdx.z];
  if(!gd.enabled) return;
  extern __shared__ __nv_bfloat16 sm[];

  const int rowBase = blockIdx.y*128;
  const int colBase = blockIdx.x*128;
  const int tid = threadIdx.x;
  const int lane = tid & 31;
  const int wid = tid >> 5;
  const int wr = wid >> 2;
  const int wc = wid & 3;

  // per-term global split sources
  const __nv_bfloat16 *Ah_g[3], *Al_g[3], *Bh_g[3], *Bl_g[3];
  #pragma unroll
  for(int t=0;t<3;t++){
    int tt = (t<gd.nterms)? t : 0;
    int as = slotOf(gd.srcA[tt]);
    Ah_g[t] = g_sph[as]; Al_g[t] = g_spl[as];
    int wg = gd.wKind[tt] ? (34+gd.wIdx[tt]) : gd.wIdx[tt];
    Bh_g[t] = g_Wth + (size_t)wg*262144;
    Bl_g[t] = g_Wtl + (size_t)wg*262144;
  }

  float acc[4][4][4];
  #pragma unroll
  for(int i=0;i<4;i++)
    #pragma unroll
    for(int j=0;j<4;j++)
      #pragma unroll
      for(int q=0;q<4;q++) acc[i][j][q]=0.f;

  const int crow = tid>>1;
  const int ccol = (tid&1)*16;
  const uint32_t smemBase = (uint32_t)__cvta_generic_to_shared(sm);
  const int chunks = gd.nterms*16;

  // issue chunk ch into stage st
  auto issue = [&](int ch, int st){
    int term = ch>>4; int k0 = (ch&15)*32;
    uint32_t sb = smemBase + (uint32_t)(st*STAGE)*2;
    size_t aoff = (size_t)(rowBase+crow)*512 + k0 + ccol;
    size_t boff = (size_t)(colBase+crow)*512 + k0 + ccol;
    uint32_t d = sb + (uint32_t)(crow*SROW + ccol)*2;
    cpa16(d,              Ah_g[term]+aoff);
    cpa16(d+16,           Ah_g[term]+aoff+8);
    cpa16(d+PART*2,       Al_g[term]+aoff);
    cpa16(d+PART*2+16,    Al_g[term]+aoff+8);
    cpa16(d+2*PART*2,     Bh_g[term]+boff);
    cpa16(d+2*PART*2+16,  Bh_g[term]+boff+8);
    cpa16(d+3*PART*2,     Bl_g[term]+boff);
    cpa16(d+3*PART*2+16,  Bl_g[term]+boff+8);
  };

  issue(0,0); CP_COMMIT;
  issue(1,1); CP_COMMIT;
  CP_WAIT(1);

  const int mi = lane>>3, wi = lane&7;
  for(int ch=0; ch<chunks; ch++){
    int st = ch&1;
    __syncthreads();
    {
      uint32_t aH = smemBase + (uint32_t)(st*STAGE)*2;
      uint32_t aL = aH + PART*2;
      uint32_t bH = aH + 2*PART*2;
      uint32_t bL = aH + 3*PART*2;
      #pragma unroll
      for(int kk=0; kk<32; kk+=16){
        uint32_t bh[4][2], bl[4][2];
        #pragma unroll
        for(int pr=0; pr<2; pr++){
          int n = wc*32 + pr*16 + ((mi>>1)<<3) + wi;
          uint32_t off = (uint32_t)(n*SROW + kk + ((mi&1)<<3))*2;
          uint32_t r0,r1,r2,r3;
          ldsm4(r0,r1,r2,r3, bH + off);
          bh[2*pr][0]=r0; bh[2*pr][1]=r1; bh[2*pr+1][0]=r2; bh[2*pr+1][1]=r3;
          ldsm4(r0,r1,r2,r3, bL + off);
          bl[2*pr][0]=r0; bl[2*pr][1]=r1; bl[2*pr+1][0]=r2; bl[2*pr+1][1]=r3;
        }
        #pragma unroll
        for(int mb=0; mb<4; mb++){
          int row = wr*64 + mb*16 + ((mi&1)<<3) + wi;
          uint32_t off = (uint32_t)(row*SROW + kk + ((mi>>1)<<3))*2;
          uint32_t ah0,ah1,ah2,ah3, al0,al1,al2,al3;
          ldsm4(ah0,ah1,ah2,ah3, aH + off);
          ldsm4(al0,al1,al2,al3, aL + off);
          #pragma unroll
          for(int nb=0; nb<4; nb++){
            mma16816(acc[mb][nb], ah0,ah1,ah2,ah3, bh[nb][0],bh[nb][1]);
            mma16816(acc[mb][nb], ah0,ah1,ah2,ah3, bl[nb][0],bl[nb][1]);
            mma16816(acc[mb][nb], al0,al1,al2,al3, bh[nb][0],bh[nb][1]);
          }
        }
      }
    }
    __syncthreads();
    if(ch+2<chunks){ issue(ch+2, st); CP_COMMIT; }
    if(ch+1<chunks){
      if(ch+2<chunks){ CP_WAIT(1); } else { CP_WAIT(0); }
    }
  }

  // ---- epilogue
  const float* bias = nullptr;
  if(gd.bKind==0)      bias = edge_b + (size_t)gd.bIdx*512;
  else if(gd.bKind==1) bias = node_b + (size_t)gd.bIdx*512;
  const float* res = (gd.resBuf>=0)? bufPtrC(gd.resBuf,inpute,inputo) : nullptr;
  float* dst = bufPtrM(gd.dstBuf);
  int dstSlot = slotOf(gd.dstBuf);
  const int g8 = lane>>2, tg = lane&3;
  #pragma unroll
  for(int mb=0;mb<4;mb++){
    #pragma unroll
    for(int nb=0;nb<4;nb++){
      int row0 = rowBase + wr*64 + mb*16 + g8;
      int col0 = colBase + wc*32 + nb*8 + tg*2;
      #pragma unroll
      for(int half=0; half<2; half++){
        int row = row0 + half*8;
        float z0 = acc[mb][nb][half*2+0] + (bias? bias[col0]:0.f);
        float z1 = acc[mb][nb][half*2+1] + (bias? bias[col0+1]:0.f);
        if(gd.actCode==1){ z0=fmaxf(z0,0.f); z1=fmaxf(z1,0.f); }
        else if(gd.actCode==2){ z0=geluf(z0); z1=geluf(z1); }
        if(res){
          float2 rv = *(const float2*)(res + (size_t)row*512 + col0);
          z0 += rv.x; z1 += rv.y;
        }
        z0 *= gd.scale; z1 *= gd.scale;
        *(float2*)(dst + (size_t)row*512 + col0) = make_float2(z0,z1);
        if(dstSlot>=0)
          store_split2(g_sph[dstSlot], g_spl[dstSlot], (size_t)row*512 + col0, z0, z1);
      }
    }
  }
}

// ---------------- flash attention (B=4,H=8,S=1024,dh=64) ----------------
__global__ void __launch_bounds__(256) attn_kernel(int c){
  if(g_node_act[c]!=0) return;
  __shared__ float qs[64][65];
  __shared__ float ks[32][65];
  __shared__ float vs[32][65];
  __shared__ float ps[64][33];
  int tid = threadIdx.x;
  int bh = blockIdx.y; int b = bh>>3, h = bh&7;
  int s0 = blockIdx.x*64;
  const float* Q = g_tt[0]; const float* K = g_tt[1]; const float* V = g_tt[2];
  size_t baseQ = ((size_t)(b*1024 + s0))*DIM + h*64;
  #pragma unroll
  for(int i=0;i<16;i++){
    int e = tid + i*256; int rr = e>>6; int dd = e&63;
    qs[rr][dd] = Q[baseQ + (size_t)rr*DIM + dd];
  }
  int rg = tid>>4, kg = tid&15;
  float acc[4][4]; float m_prev[4], lsum[4];
  #pragma unroll
  for(int i=0;i<4;i++){
    m_prev[i]=-1e30f; lsum[i]=0.f;
    #pragma unroll
    for(int j=0;j<4;j++) acc[i][j]=0.f;
  }
  for(int kt=0;kt<32;kt++){
    __syncthreads();
    size_t baseK = ((size_t)(b*1024 + kt*32))*DIM + h*64;
    #pragma unroll
    for(int i=0;i<8;i++){
      int e = tid + i*256; int rr = e>>6; int dd = e&63;
      ks[rr][dd] = K[baseK + (size_t)rr*DIM + dd];
      vs[rr][dd] = V[baseK + (size_t)rr*DIM + dd];
    }
    __syncthreads();
    float sc[4][2];
    #pragma unroll
    for(int i=0;i<4;i++){ sc[i][0]=0.f; sc[i][1]=0.f; }
    #pragma unroll 4
    for(int d=0;d<64;d++){
      float rk0 = ks[kg*2+0][d], rk1 = ks[kg*2+1][d];
      #pragma unroll
      for(int i=0;i<4;i++){
        float rq = qs[rg*4+i][d];
        sc[i][0] = fmaf(rq,rk0,sc[i][0]);
        sc[i][1] = fmaf(rq,rk1,sc[i][1]);
      }
    }
    #pragma unroll
    for(int i=0;i<4;i++){
      float s0v = sc[i][0]*0.125f, s1v = sc[i][1]*0.125f;
      float mloc = fmaxf(s0v,s1v);
      #pragma unroll
      for(int o=1;o<16;o<<=1) mloc = fmaxf(mloc, __shfl_xor_sync(0xffffffffu,mloc,o));
      float m_new = fmaxf(m_prev[i], mloc);
      float p0 = __expf(s0v-m_new), p1 = __expf(s1v-m_new);
      ps[rg*4+i][kg*2+0]=p0; ps[rg*4+i][kg*2+1]=p1;
      float lloc = p0+p1;
      #pragma unroll
      for(int o=1;o<16;o<<=1) lloc += __shfl_xor_sync(0xffffffffu,lloc,o);
      float corr = __expf(m_prev[i]-m_new);
      lsum[i] = lsum[i]*corr + lloc;
      m_prev[i] = m_new;
      #pragma unroll
      for(int j=0;j<4;j++) acc[i][j]*=corr;
    }
    __syncthreads();
    #pragma unroll 4
    for(int j=0;j<32;j++){
      float v0=vs[j][kg*4+0], v1=vs[j][kg*4+1], v2=vs[j][kg*4+2], v3=vs[j][kg*4+3];
      #pragma unroll
      for(int i=0;i<4;i++){
        float p = ps[rg*4+i][j];
        acc[i][0]=fmaf(p,v0,acc[i][0]); acc[i][1]=fmaf(p,v1,acc[i][1]);
        acc[i][2]=fmaf(p,v2,acc[i][2]); acc[i][3]=fmaf(p,v3,acc[i][3]);
      }
    }
  }
  #pragma unroll
  for(int i=0;i<4;i++){
    float inv = 1.f/lsum[i];
    size_t o = ((size_t)(b*1024 + s0 + rg*4 + i))*DIM + h*64 + kg*4;
    store_split2(g_sph[12], g_spl[12], o,   acc[i][0]*inv, acc[i][1]*inv);
    store_split2(g_sph[12], g_spl[12], o+2, acc[i][2]*inv, acc[i][3]*inv);
  }
}

// ---------------- elementwise node ops (acts 2,4,5,6,7) ----------------
__global__ void post_elt(int c, const float* __restrict__ node_g, const float* __restrict__ node_beta){
  int act = g_node_act[c];
  if(act==0||act==1||act==3) return;
  float aw = g_node_aw[c];
  int row=blockIdx.x, t=threadIdx.x;
  size_t off=(size_t)row*DIM;
  const float* q=g_qkv[0]+off; const float* k=g_qkv[1]+off; const float* v=g_qkv[2]+off;
  float* o = g_outbuf[c]+off;
  if(act==4){
    o[t]     = aw*(q[t]*sigmoidf(k[t]) + v[t]);
    o[t+256] = aw*(q[t+256]*sigmoidf(k[t+256]) + v[t+256]);
    return;
  }
  if(act==5){
    const float* tt = g_tt[0]+off;
    o[t]=aw*(q[t]+tt[t]); o[t+256]=aw*(q[t+256]+tt[t+256]);
    return;
  }
  if(act==6){
    o[t]=aw*(q[t]+k[t]); o[t+256]=aw*(q[t+256]+k[t+256]);
    return;
  }
  float a,b;
  if(act==2){ a=q[t]+k[t]+v[t]; b=q[t+256]+k[t+256]+v[t+256]; }
  else      { a=q[t];           b=q[t+256]; }
  float s = blockReduceSum(a+b);
  float mean = s*(1.f/512.f);
  float da=a-mean, db=b-mean;
  float s2 = blockReduceSum(da*da+db*db);
  float rstd = rsqrtf(s2*(1.f/512.f)+1e-6f);
  const float* g  = node_g    + (size_t)c*DIM;
  const float* be = node_beta + (size_t)c*DIM;
  o[t]     = aw*(da*rstd*g[t]     + be[t]);
  o[t+256] = aw*(db*rstd*g[t+256] + be[t+256]);
}

// ---------------- final: sum remaining nodes + LN ----------------
__global__ void final_kernel(const float* __restrict__ og, const float* __restrict__ obe, float* __restrict__ out){
  int row=blockIdx.x, t=threadIdx.x;
  int mask = g_rem_mask;
  size_t off=(size_t)row*DIM;
  float a=0.f, b=0.f;
  #pragma unroll
  for(int i=0;i<8;i++) if((mask>>i)&1){
    a += g_outbuf[i][off+t];
    b += g_outbuf[i][off+t+256];
  }
  float s = blockReduceSum(a+b);
  float mean = s*(1.f/512.f);
  float da=a-mean, db=b-mean;
  float s2 = blockReduceSum(da*da+db*db);
  float rstd = rsqrtf(s2*(1.f/512.f)+1e-6f);
  out[off+t]     = da*rstd*og[t]     + obe[t];
  out[off+t+256] = db*rstd*og[t+256] + obe[t+256];
}

extern "C" void kernel_launch(void* const* d_in, const int* in_sizes, int n_in,
                              void* d_out, int out_size) {
  (void)in_sizes; (void)n_in; (void)out_size;
  const float* inpute    = (const float*)d_in[0];
  const float* inputo    = (const float*)d_in[1];
  const float* node_p    = (const float*)d_in[2];
  const float* edge_p    = (const float*)d_in[3];
  const float* edge_W    = (const float*)d_in[4];
  const float* edge_b    = (const float*)d_in[5];
  const float* edge_g    = (const float*)d_in[6];
  const float* edge_beta = (const float*)d_in[7];
  const float* node_W    = (const float*)d_in[8];
  const float* node_b    = (const float*)d_in[9];
  const float* node_g    = (const float*)d_in[10];
  const float* node_beta = (const float*)d_in[11];
  const float* out_g     = (const float*)d_in[12];
  const float* out_beta  = (const float*)d_in[13];
  float* out = (float*)d_out;

  const int gemmSmem = 2*STAGE*(int)sizeof(__nv_bfloat16); // 81920 bytes
  cudaFuncSetAttribute(gemm_kernel, cudaFuncAttributeMaxDynamicSharedMemorySize, gemmSmem);

  route_kernel<<<1,1>>>(node_p, edge_p);
  convin_kernel<<<dim3(2048,2),256>>>(inpute, inputo);
  convw_kernel<<<dim3(16,16,66),256>>>(edge_W, node_W);
  for(int c=0;c<8;c++){
    prep_kernel<<<dim3(NROWS,1,3),256>>>(c, inpute, inputo, edge_g, edge_beta);
    gemm_kernel<<<dim3(4,32,3),256,gemmSmem>>>(c,0,inpute,inputo,edge_b,node_b);
    lnq_kernel<<<NROWS,256>>>(c, node_g, node_beta);
    gemm_kernel<<<dim3(4,32,3),256,gemmSmem>>>(c,3,inpute,inputo,edge_b,node_b);
    attn_kernel<<<dim3(16,32),256>>>(c);
    mul_kernel<<<NROWS,256>>>(c);
    gemm_kernel<<<dim3(4,32,1),256,gemmSmem>>>(c,6,inpute,inputo,edge_b,node_b);
    post_elt<<<NROWS,256>>>(c, node_g, node_beta);
  }
  final_kernel<<<NROWS,256>>>(out_g, out_beta, out);
}

// round 9
// speedup vs baseline: 1.2545x; 1.2545x over previous
#include <cuda_runtime.h>
#include <cuda_bf16.h>
#include <math.h>
#include <stdint.h>

#define NROWS 4096
#define DIM 512

// ---------------- descriptors ----------------
struct ERole { int enabled; int src; int e; int op; float w; };
struct GemmDesc {
  int enabled, nterms, mul;
  int srcA[3];
  int wKind[3], wIdx[3];
  int bKind, bIdx;
  int actCode;          // 0 none, 1 relu, 2 gelu
  int resBuf, dstBuf;
  float scale;
};

__device__ ERole    g_erole[8][3];
__device__ GemmDesc g_gd[8][7];
__device__ int      g_node_act[8];
__device__ float    g_node_aw[8];
__device__ int      g_rem_mask;

// ---------------- big scratch buffers ----------------
__device__ float g_outbuf[8][NROWS*DIM];
__device__ float g_qkv[3][NROWS*DIM];
__device__ float g_prep[3][NROWS*DIM];
__device__ float g_tt[3][NROWS*DIM];
__device__ float g_lnq[NROWS*DIM];
__device__ float g_attn[NROWS*DIM];

// transposed bf16 weights: [w][n*512+k], hi and lo. w: 0..33 edge, 34..65 node
__device__ __nv_bfloat16 g_Wth[66u*262144u];
__device__ __nv_bfloat16 g_Wtl[66u*262144u];

// buffer id map: 0 inpute, 1 inputo, 2..9 outbuf, 10..12 qkv, 13..15 prep, 16..18 tt, 19 lnq, 20 attn
__device__ __forceinline__ const float* bufPtrC(int id, const float* inpute, const float* inputo){
  if(id==0) return inpute;
  if(id==1) return inputo;
  if(id<10) return g_outbuf[id-2];
  if(id<13) return g_qkv[id-10];
  if(id<16) return g_prep[id-13];
  if(id<19) return g_tt[id-16];
  if(id==19) return g_lnq;
  return g_attn;
}
__device__ __forceinline__ float* bufPtrM(int id){
  if(id<10) return g_outbuf[id-2];
  if(id<13) return g_qkv[id-10];
  if(id<16) return g_prep[id-13];
  if(id<19) return g_tt[id-16];
  if(id==19) return g_lnq;
  return g_attn;
}

__device__ __forceinline__ float geluf(float x){
  float inner = 0.7978845608028654f*(x + 0.044715f*x*x*x);
  return 0.5f*x*(1.f+tanhf(inner));
}
__device__ __forceinline__ float sigmoidf(float x){ return 1.f/(1.f+expf(-x)); }

__device__ __forceinline__ float warpReduceSum(float v){
  #pragma unroll
  for(int o=16;o;o>>=1) v += __shfl_xor_sync(0xffffffffu, v, o);
  return v;
}

// ---------------- routing ----------------
__device__ void selrange(const float* p, int lo, int hi, int& sel, float& w){
  int bi=lo; float bv=p[lo];
  for(int i=lo+1;i<hi;i++) if(p[i]>bv){bv=p[i];bi=i;}
  float s=0.f;
  for(int i=lo;i<hi;i++) s += expf(p[i]-bv);
  sel=bi; w=1.f/s;
}

__device__ void fillRole(int c,int role,int sel,float w,int lind,int snode,int& processed,int computeEnabled){
  int se = sel/5, op = sel%5;
  int inn = (se==0)? -2 : snode+se;
  if(inn>=0) processed |= (1<<inn);
  int src = (inn==-2)?0 : ((inn==-1)?1 : (2+inn));
  ERole er; er.enabled=computeEnabled; er.src=src; er.e=lind+se; er.op=op; er.w=w;
  g_erole[c][role]=er;
}

__device__ void setGemm(int c,int slot,int src0,int wKind0,int wIdx0,int bKind,int bIdx,
                        int actCode,int resBuf,int dstBuf,float scale){
  GemmDesc gd;
  gd.enabled=1; gd.nterms=1; gd.mul=0;
  gd.srcA[0]=src0; gd.srcA[1]=0; gd.srcA[2]=0;
  gd.wKind[0]=wKind0; gd.wIdx[0]=wIdx0;
  gd.wKind[1]=0; gd.wIdx[1]=0; gd.wKind[2]=0; gd.wIdx[2]=0;
  gd.bKind=bKind; gd.bIdx=bIdx;
  gd.actCode=actCode; gd.resBuf=resBuf; gd.dstBuf=dstBuf; gd.scale=scale;
  g_gd[c][slot]=gd;
}

__global__ void route_kernel(const float* __restrict__ node_p, const float* __restrict__ edge_p){
  if(threadIdx.x!=0 || blockIdx.x!=0) return;
  int processed = 0;
  int lind = 0;
  for(int c=0;c<8;c++){
    for(int s=0;s<7;s++) g_gd[c][s].enabled=0;
    for(int r=0;r<3;r++) g_erole[c][r].enabled=0;

    int nsrc = (c+2<5)? c+2 : 5;
    int snode = c - nsrc;
    int L = nsrc*5;
    const float* ep0 = edge_p + lind*5;
    const float* ep1 = edge_p + 170 + lind*5;
    const float* ep2 = edge_p + 340 + lind*5;
    const float* np  = node_p + c*8;

    int act=0; { float b=np[0]; for(int i=1;i<8;i++) if(np[i]>b){b=np[i];act=i;} }
    float aw;
    { float m=np[0]; for(int i=1;i<8;i++) m=fmaxf(m,np[i]);
      float s=0.f; for(int i=0;i<8;i++) s+=expf(np[i]-m);
      aw = expf(np[act]-m)/s; }
    g_node_act[c]=act; g_node_aw[c]=aw;

    int qsel; float qw;
    selrange(ep0, 5, L, qsel, qw);
    fillRole(c,0,qsel,qw,lind,snode,processed,1);

    int ksel = -1;
    if(act<7){
      int lo = (act>0)?5:0;
      float kw;
      selrange(ep1, lo, L, ksel, kw);
      fillRole(c,1,ksel,kw,lind,snode,processed,1);
    }
    if(act<5){
      int vsel; float vw;
      if(act==0 && (ksel/5)==0){
        selrange(ep2, 0, 5, vsel, vw);
      } else {
        int lo = (act>0)?5:0;
        selrange(ep2, lo, L, vsel, vw);
      }
      fillRole(c,2,vsel,vw,lind,snode,processed,(act!=1)?1:0);
    }

    for(int r2=0;r2<3;r2++){
      ERole er = g_erole[c][r2];
      if(er.enabled && er.op!=4){
        int ac = (er.op==0)?1:((er.op==1)?2:0);
        setGemm(c, r2, 13+r2, 0, er.e, 0, er.e, ac, -1, 10+r2, er.w);
      }
    }

    int cw = c*4;
    if(act==0){
      setGemm(c,3,19,1,cw+0,1,cw+0,0,-1,16,1.f);
      setGemm(c,4,11,1,cw+1,1,cw+1,0,-1,17,1.f);
      setGemm(c,5,12,1,cw+2,1,cw+2,0,-1,18,1.f);
      setGemm(c,6,20,1,cw+3,1,cw+3,0,10,2+c,aw);
    } else if(act==1){
      setGemm(c,3,10,1,cw+0,1,cw+0,2,-1,16,1.f);
      setGemm(c,4,11,1,cw+1,1,cw+1,0,-1,17,1.f);
      setGemm(c,6,16,1,cw+3,1,cw+3,0,10,2+c,aw);
      g_gd[c][6].mul=1; g_gd[c][6].srcA[1]=17;
    } else if(act==3){
      setGemm(c,3,10,1,cw+0,-1,0,1,-1,16,1.f);
      g_gd[c][3].nterms=3;
      g_gd[c][3].srcA[1]=11; g_gd[c][3].srcA[2]=12;
      g_gd[c][3].wKind[1]=1; g_gd[c][3].wIdx[1]=cw+1;
      g_gd[c][3].wKind[2]=1; g_gd[c][3].wIdx[2]=cw+2;
      setGemm(c,6,16,1,cw+3,1,cw+3,0,10,2+c,aw);
    } else if(act==5){
      setGemm(c,3,11,1,cw+1,1,cw+1,2,-1,16,1.f);
    }

    lind += nsrc;
  }
  g_rem_mask = (~processed) & 0xFF;
}

// ---------------- weight conversion: fp32 [k][n] -> bf16 hi/lo transposed [n][k] ----------------
__global__ void convw_kernel(const float* __restrict__ eW, const float* __restrict__ nW){
  __shared__ float tile[32][33];
  int w = blockIdx.z;
  const float* src = (w<34) ? eW + (size_t)w*262144 : nW + (size_t)(w-34)*262144;
  int k0 = blockIdx.x*32, n0 = blockIdx.y*32;
  int tr = threadIdx.x>>3;
  int tc = (threadIdx.x&7)*4;
  float4 v = *(const float4*)(src + (size_t)(k0+tr)*512 + n0+tc);
  tile[tr][tc+0]=v.x; tile[tr][tc+1]=v.y; tile[tr][tc+2]=v.z; tile[tr][tc+3]=v.w;
  __syncthreads();
  int nr = threadIdx.x>>3;
  int kc = (threadIdx.x&7)*4;
  union { __nv_bfloat16 b[4]; uint2 u; } ph, pl;
  #pragma unroll
  for(int j=0;j<4;j++){
    float x = tile[kc+j][nr];
    __nv_bfloat16 h = __float2bfloat16(x);
    ph.b[j] = h;
    pl.b[j] = __float2bfloat16(x - __bfloat162float(h));
  }
  size_t off = (size_t)w*262144 + (size_t)(n0+nr)*512 + k0+kc;
  *(uint2*)(g_Wth + off) = ph.u;
  *(uint2*)(g_Wtl + off) = pl.u;
}

// ---------------- edge prep (warp-per-row) ----------------
__global__ void prep_kernel(int c, const float* __restrict__ inpute, const float* __restrict__ inputo,
                            const float* __restrict__ edge_g, const float* __restrict__ edge_beta){
  int role = blockIdx.z;
  ERole er = g_erole[c][role];
  if(!er.enabled) return;
  int wid = threadIdx.x>>5, lane = threadIdx.x&31;
  int row = blockIdx.x*8 + wid;
  const float* x = bufPtrC(er.src, inpute, inputo) + (size_t)row*DIM;
  float4 v[4];
  #pragma unroll
  for(int j=0;j<4;j++) v[j] = *(const float4*)(x + lane*4 + j*128);
  if(er.op==4){
    float* d = g_qkv[role] + (size_t)row*DIM;
    #pragma unroll
    for(int j=0;j<4;j++){
      float4 o; o.x=er.w*v[j].x; o.y=er.w*v[j].y; o.z=er.w*v[j].z; o.w=er.w*v[j].w;
      *(float4*)(d + lane*4 + j*128) = o;
    }
    return;
  }
  if(er.op==3){
    float* d = g_prep[role] + (size_t)row*DIM;
    #pragma unroll
    for(int j=0;j<4;j++) *(float4*)(d + lane*4 + j*128) = v[j];
    return;
  }
  float s=0.f;
  #pragma unroll
  for(int j=0;j<4;j++) s += v[j].x+v[j].y+v[j].z+v[j].w;
  float mean = warpReduceSum(s)*(1.f/512.f);
  float s2=0.f;
  #pragma unroll
  for(int j=0;j<4;j++){
    float a=v[j].x-mean,b=v[j].y-mean,cc=v[j].z-mean,dd=v[j].w-mean;
    s2 += a*a+b*b+cc*cc+dd*dd;
  }
  float rstd = rsqrtf(warpReduceSum(s2)*(1.f/512.f)+1e-6f);
  const float* g  = edge_g    + (size_t)er.e*DIM;
  const float* be = edge_beta + (size_t)er.e*DIM;
  float* d = g_prep[role] + (size_t)row*DIM;
  #pragma unroll
  for(int j=0;j<4;j++){
    int col = lane*4 + j*128;
    float4 gv = *(const float4*)(g+col);
    float4 bv = *(const float4*)(be+col);
    float4 o;
    o.x=(v[j].x-mean)*rstd*gv.x+bv.x; o.y=(v[j].y-mean)*rstd*gv.y+bv.y;
    o.z=(v[j].z-mean)*rstd*gv.z+bv.z; o.w=(v[j].w-mean)*rstd*gv.w+bv.w;
    *(float4*)(d+col)=o;
  }
}

// ---------------- LN(q) for MHA (warp-per-row) ----------------
__global__ void lnq_kernel(int c, const float* __restrict__ node_g, const float* __restrict__ node_beta){
  if(g_node_act[c]!=0) return;
  int wid = threadIdx.x>>5, lane = threadIdx.x&31;
  int row = blockIdx.x*8 + wid;
  const float* x = g_qkv[0] + (size_t)row*DIM;
  float4 v[4];
  #pragma unroll
  for(int j=0;j<4;j++) v[j] = *(const float4*)(x + lane*4 + j*128);
  float s=0.f;
  #pragma unroll
  for(int j=0;j<4;j++) s += v[j].x+v[j].y+v[j].z+v[j].w;
  float mean = warpReduceSum(s)*(1.f/512.f);
  float s2=0.f;
  #pragma unroll
  for(int j=0;j<4;j++){
    float a=v[j].x-mean,b=v[j].y-mean,cc=v[j].z-mean,dd=v[j].w-mean;
    s2 += a*a+b*b+cc*cc+dd*dd;
  }
  float rstd = rsqrtf(warpReduceSum(s2)*(1.f/512.f)+1e-6f);
  const float* g  = node_g    + (size_t)c*DIM;
  const float* be = node_beta + (size_t)c*DIM;
  float* d = g_lnq + (size_t)row*DIM;
  #pragma unroll
  for(int j=0;j<4;j++){
    int col = lane*4 + j*128;
    float4 gv = *(const float4*)(g+col);
    float4 bv = *(const float4*)(be+col);
    float4 o;
    o.x=(v[j].x-mean)*rstd*gv.x+bv.x; o.y=(v[j].y-mean)*rstd*gv.y+bv.y;
    o.z=(v[j].z-mean)*rstd*gv.z+bv.z; o.w=(v[j].w-mean)*rstd*gv.w+bv.w;
    *(float4*)(d+col)=o;
  }
}

// ---------------- tensor-core GEMM (R4 design: register staging, on-the-fly A split) ----------------
#define SMS 40
#define BUFE (128*SMS)

__device__ __forceinline__ void mma16816(float* c, uint32_t a0,uint32_t a1,uint32_t a2,uint32_t a3,
                                         uint32_t b0, uint32_t b1){
  asm volatile("mma.sync.aligned.m16n8k16.row.col.f32.bf16.bf16.f32 "
    "{%0,%1,%2,%3}, {%4,%5,%6,%7}, {%8,%9}, {%0,%1,%2,%3};"
    : "+f"(c[0]),"+f"(c[1]),"+f"(c[2]),"+f"(c[3])
    : "r"(a0),"r"(a1),"r"(a2),"r"(a3),"r"(b0),"r"(b1));
}

__global__ void __launch_bounds__(256,1) gemm_kernel(int c,int slotBase,
  const float* __restrict__ inpute,const float* __restrict__ inputo,
  const float* __restrict__ edge_b,const float* __restrict__ node_b)
{
  GemmDesc gd = g_gd[c][slotBase + blockIdx.z];
  if(!gd.enabled) return;
  extern __shared__ __nv_bfloat16 sm[];
  __nv_bfloat16* Ah = sm;
  __nv_bfloat16* Al = sm + 2*BUFE;
  __nv_bfloat16* Bh = sm + 4*BUFE;
  __nv_bfloat16* Bl = sm + 6*BUFE;

  const int rowBase = blockIdx.y*128;
  const int colBase = blockIdx.x*128;
  const int tid = threadIdx.x;
  const int lane = tid & 31;
  const int wid = tid >> 5;
  const int wr = wid >> 2;
  const int wc = wid & 3;
  const int g8 = lane >> 2;
  const int tg = lane & 3;

  const float* Aterm[3];
  const __nv_bfloat16* Whp[3];
  const __nv_bfloat16* Wlp[3];
  for(int t=0;t<gd.nterms;t++){
    Aterm[t] = bufPtrC(gd.srcA[t],inpute,inputo);
    int wg = gd.wKind[t] ? (34+gd.wIdx[t]) : gd.wIdx[t];
    Whp[t] = g_Wth + (size_t)wg*262144;
    Wlp[t] = g_Wtl + (size_t)wg*262144;
  }
  const float* A2base = gd.mul ? bufPtrC(gd.srcA[1],inpute,inputo) : nullptr;

  float acc[4][4][4];
  #pragma unroll
  for(int i=0;i<4;i++)
    #pragma unroll
    for(int j=0;j<4;j++)
      #pragma unroll
      for(int q=0;q<4;q++) acc[i][j][q]=0.f;

  const int arL = (tid>>3);
  const int akL = (tid&7)*4;
  const int bnL = (tid>>2);
  const int bkL = (tid&3)*8;

  float4 pa[4]; uint4 pbh[2], pbl[2];
  const int totalChunks = gd.nterms*16;

  {
    const float* A = Aterm[0];
    #pragma unroll
    for(int it=0;it<4;it++){
      int r = arL + it*32;
      pa[it] = *(const float4*)(A + (size_t)(rowBase+r)*512 + akL);
      if(A2base){
        float4 u = *(const float4*)(A2base + (size_t)(rowBase+r)*512 + akL);
        pa[it].x*=u.x; pa[it].y*=u.y; pa[it].z*=u.z; pa[it].w*=u.w;
      }
    }
    #pragma unroll
    for(int p=0;p<2;p++){
      int n = bnL + p*64;
      pbh[p] = *(const uint4*)(Whp[0] + (size_t)(colBase+n)*512 + bkL);
      pbl[p] = *(const uint4*)(Wlp[0] + (size_t)(colBase+n)*512 + bkL);
    }
  }
  {
    #pragma unroll
    for(int it=0;it<4;it++){
      int r = arL + it*32;
      union { __nv_bfloat16 b[4]; uint2 u; } ph, pl;
      float xs[4]={pa[it].x,pa[it].y,pa[it].z,pa[it].w};
      #pragma unroll
      for(int j=0;j<4;j++){
        __nv_bfloat16 h = __float2bfloat16(xs[j]);
        ph.b[j]=h; pl.b[j]=__float2bfloat16(xs[j]-__bfloat162float(h));
      }
      *(uint2*)(Ah + r*SMS + akL) = ph.u;
      *(uint2*)(Al + r*SMS + akL) = pl.u;
    }
    #pragma unroll
    for(int p=0;p<2;p++){
      int n = bnL + p*64;
      *(uint2*)(Bh + n*SMS + bkL)     = make_uint2(pbh[p].x, pbh[p].y);
      *(uint2*)(Bh + n*SMS + bkL + 4) = make_uint2(pbh[p].z, pbh[p].w);
      *(uint2*)(Bl + n*SMS + bkL)     = make_uint2(pbl[p].x, pbl[p].y);
      *(uint2*)(Bl + n*SMS + bkL + 4) = make_uint2(pbl[p].z, pbl[p].w);
    }
  }
  __syncthreads();

  int buf = 0;
  for(int ch=1; ch<=totalChunks; ch++){
    if(ch<totalChunks){
      int term = ch>>4; int k0 = (ch&15)*32;
      const float* A = Aterm[term];
      #pragma unroll
      for(int it=0;it<4;it++){
        int r = arL + it*32;
        pa[it] = *(const float4*)(A + (size_t)(rowBase+r)*512 + k0 + akL);
        if(A2base){
          float4 u = *(const float4*)(A2base + (size_t)(rowBase+r)*512 + k0 + akL);
          pa[it].x*=u.x; pa[it].y*=u.y; pa[it].z*=u.z; pa[it].w*=u.w;
        }
      }
      #pragma unroll
      for(int p=0;p<2;p++){
        int n = bnL + p*64;
        pbh[p] = *(const uint4*)(Whp[term] + (size_t)(colBase+n)*512 + k0 + bkL);
        pbl[p] = *(const uint4*)(Wlp[term] + (size_t)(colBase+n)*512 + k0 + bkL);
      }
    }
    {
      const __nv_bfloat16* ah_ = Ah + buf*BUFE;
      const __nv_bfloat16* al_ = Al + buf*BUFE;
      const __nv_bfloat16* bh_ = Bh + buf*BUFE;
      const __nv_bfloat16* bl_ = Bl + buf*BUFE;
      #pragma unroll
      for(int kk=0;kk<32;kk+=16){
        uint32_t bh0[4],bh1[4],bl0[4],bl1[4];
        #pragma unroll
        for(int nb=0;nb<4;nb++){
          int o = (wc*32+nb*8+g8)*SMS + kk + tg*2;
          bh0[nb]=*(const uint32_t*)(bh_+o); bh1[nb]=*(const uint32_t*)(bh_+o+8);
          bl0[nb]=*(const uint32_t*)(bl_+o); bl1[nb]=*(const uint32_t*)(bl_+o+8);
        }
        #pragma unroll
        for(int mb=0;mb<4;mb++){
          int o = (wr*64+mb*16+g8)*SMS + kk + tg*2;
          uint32_t ah0=*(const uint32_t*)(ah_+o);
          uint32_t ah1=*(const uint32_t*)(ah_+o+8*SMS);
          uint32_t ah2=*(const uint32_t*)(ah_+o+8);
          uint32_t ah3=*(const uint32_t*)(ah_+o+8*SMS+8);
          uint32_t al0=*(const uint32_t*)(al_+o);
          uint32_t al1=*(const uint32_t*)(al_+o+8*SMS);
          uint32_t al2=*(const uint32_t*)(al_+o+8);
          uint32_t al3=*(const uint32_t*)(al_+o+8*SMS+8);
          #pragma unroll
          for(int nb=0;nb<4;nb++){
            mma16816(acc[mb][nb], ah0,ah1,ah2,ah3, bh0[nb],bh1[nb]);
            mma16816(acc[mb][nb], ah0,ah1,ah2,ah3, bl0[nb],bl1[nb]);
            mma16816(acc[mb][nb], al0,al1,al2,al3, bh0[nb],bh1[nb]);
          }
        }
      }
    }
    if(ch<totalChunks){
      int nb2 = buf^1;
      #pragma unroll
      for(int it=0;it<4;it++){
        int r = arL + it*32;
        union { __nv_bfloat16 b[4]; uint2 u; } ph, pl;
        float xs[4]={pa[it].x,pa[it].y,pa[it].z,pa[it].w};
        #pragma unroll
        for(int j=0;j<4;j++){
          __nv_bfloat16 h = __float2bfloat16(xs[j]);
          ph.b[j]=h; pl.b[j]=__float2bfloat16(xs[j]-__bfloat162float(h));
        }
        *(uint2*)(Ah + nb2*BUFE + r*SMS + akL) = ph.u;
        *(uint2*)(Al + nb2*BUFE + r*SMS + akL) = pl.u;
      }
      #pragma unroll
      for(int p=0;p<2;p++){
        int n = bnL + p*64;
        *(uint2*)(Bh + nb2*BUFE + n*SMS + bkL)     = make_uint2(pbh[p].x, pbh[p].y);
        *(uint2*)(Bh + nb2*BUFE + n*SMS + bkL + 4) = make_uint2(pbh[p].z, pbh[p].w);
        *(uint2*)(Bl + nb2*BUFE + n*SMS + bkL)     = make_uint2(pbl[p].x, pbl[p].y);
        *(uint2*)(Bl + nb2*BUFE + n*SMS + bkL + 4) = make_uint2(pbl[p].z, pbl[p].w);
      }
      __syncthreads();
      buf = nb2;
    }
  }

  const float* bias = nullptr;
  if(gd.bKind==0)      bias = edge_b + (size_t)gd.bIdx*512;
  else if(gd.bKind==1) bias = node_b + (size_t)gd.bIdx*512;
  const float* res = (gd.resBuf>=0)? bufPtrC(gd.resBuf,inpute,inputo) : nullptr;
  float* dst = bufPtrM(gd.dstBuf);
  #pragma unroll
  for(int mb=0;mb<4;mb++){
    #pragma unroll
    for(int nb=0;nb<4;nb++){
      int row0 = rowBase + wr*64 + mb*16 + g8;
      int col0 = colBase + wc*32 + nb*8 + tg*2;
      #pragma unroll
      for(int half=0; half<2; half++){
        int row = row0 + half*8;
        float z0 = acc[mb][nb][half*2+0] + (bias? bias[col0]:0.f);
        float z1 = acc[mb][nb][half*2+1] + (bias? bias[col0+1]:0.f);
        if(gd.actCode==1){ z0=fmaxf(z0,0.f); z1=fmaxf(z1,0.f); }
        else if(gd.actCode==2){ z0=geluf(z0); z1=geluf(z1); }
        if(res){
          float2 rv = *(const float2*)(res + (size_t)row*512 + col0);
          z0 += rv.x; z1 += rv.y;
        }
        float2 ov; ov.x = gd.scale*z0; ov.y = gd.scale*z1;
        *(float2*)(dst + (size_t)row*512 + col0) = ov;
      }
    }
  }
}

// ---------------- tensor-core flash attention ----------------
// B=4,H=8,S=1024,dh=64, masks all false. 128 q-rows per block, 8 warps (16 q each),
// 64-key chunks. hi/lo split (3-mma) on QK^T and PV. V via ldmatrix.trans.
#define ASROW 72
#define AQ_H 0
#define AQ_L 9216
#define AK_H 18432
#define AK_L 23040
#define AV_H 27648
#define AV_L 32256
#define ATTN_SMEM_ELEMS 36864

__device__ __forceinline__ void ldsm4(uint32_t& r0,uint32_t& r1,uint32_t& r2,uint32_t& r3, uint32_t saddr){
  asm volatile("ldmatrix.sync.aligned.m8n8.x4.shared.b16 {%0,%1,%2,%3}, [%4];"
    : "=r"(r0),"=r"(r1),"=r"(r2),"=r"(r3) : "r"(saddr));
}
__device__ __forceinline__ void ldsm4t(uint32_t& r0,uint32_t& r1,uint32_t& r2,uint32_t& r3, uint32_t saddr){
  asm volatile("ldmatrix.sync.aligned.m8n8.x4.trans.shared.b16 {%0,%1,%2,%3}, [%4];"
    : "=r"(r0),"=r"(r1),"=r"(r2),"=r"(r3) : "r"(saddr));
}
__device__ __forceinline__ uint32_t packbf2(float a, float b){
  __nv_bfloat162 h; h.x=__float2bfloat16(a); h.y=__float2bfloat16(b);
  return *(uint32_t*)&h;
}
__device__ __forceinline__ void split2(float a, float b, uint32_t& hi, uint32_t& lo){
  __nv_bfloat16 ha=__float2bfloat16(a), hb=__float2bfloat16(b);
  __nv_bfloat162 hh; hh.x=ha; hh.y=hb; hi = *(uint32_t*)&hh;
  __nv_bfloat162 ll; ll.x=__float2bfloat16(a-__bfloat162float(ha));
  ll.y=__float2bfloat16(b-__bfloat162float(hb)); lo = *(uint32_t*)&ll;
}

__global__ void __launch_bounds__(256,1) attn_kernel(int c){
  if(g_node_act[c]!=0) return;
  extern __shared__ __nv_bfloat16 asm_[];
  const int tid = threadIdx.x;
  const int lane = tid & 31;
  const int wid = tid >> 5;
  const int mi = lane>>3, wi = lane&7;
  const int g8 = lane>>2, tg = lane&3;
  const int bh = blockIdx.y; const int b = bh>>3, h = bh&7;
  const int q0 = blockIdx.x*128;
  const float* Q = g_tt[0]; const float* K = g_tt[1]; const float* V = g_tt[2];
  const uint32_t smemBase = (uint32_t)__cvta_generic_to_shared(asm_);

  // load Q tile 128x64 -> split smem
  {
    int row = tid>>1;           // 0..127
    int col0 = (tid&1)*32;
    const float* src = Q + ((size_t)(b*1024+q0+row))*DIM + h*64 + col0;
    #pragma unroll
    for(int j=0;j<8;j++){
      float4 v = *(const float4*)(src + j*4);
      uint32_t h0,l0,h1,l1;
      split2(v.x,v.y,h0,l0); split2(v.z,v.w,h1,l1);
      int o = row*ASROW + col0 + j*4;
      *(uint32_t*)(asm_+AQ_H+o)   = h0; *(uint32_t*)(asm_+AQ_H+o+2) = h1;
      *(uint32_t*)(asm_+AQ_L+o)   = l0; *(uint32_t*)(asm_+AQ_L+o+2) = l1;
    }
  }
  __syncthreads();

  // preload Q fragments (invariant over chunks): 4 ksteps
  uint32_t qh[4][4], ql[4][4];
  {
    int row = wid*16 + ((mi&1)<<3) + wi;
    #pragma unroll
    for(int ks=0;ks<4;ks++){
      uint32_t off = (uint32_t)(row*ASROW + ks*16 + ((mi>>1)<<3))*2;
      ldsm4(qh[ks][0],qh[ks][1],qh[ks][2],qh[ks][3], smemBase + AQ_H*2 + off);
      ldsm4(ql[ks][0],ql[ks][1],ql[ks][2],ql[ks][3], smemBase + AQ_L*2 + off);
    }
  }

  float o_acc[8][4];
  #pragma unroll
  for(int nb=0;nb<8;nb++)
    #pragma unroll
    for(int q=0;q<4;q++) o_acc[nb][q]=0.f;
  float m_st[2] = {-1e30f,-1e30f};
  float l_st[2] = {0.f,0.f};

  for(int chunk=0; chunk<16; chunk++){
    __syncthreads();
    // load K,V 64x64 chunk -> split smem
    {
      int key = tid>>2;            // 0..63
      int col0 = (tid&3)*16;
      size_t base = ((size_t)(b*1024 + chunk*64 + key))*DIM + h*64 + col0;
      #pragma unroll
      for(int j=0;j<4;j++){
        float4 kv = *(const float4*)(K + base + j*4);
        float4 vv = *(const float4*)(V + base + j*4);
        uint32_t h0,l0,h1,l1;
        int o = key*ASROW + col0 + j*4;
        split2(kv.x,kv.y,h0,l0); split2(kv.z,kv.w,h1,l1);
        *(uint32_t*)(asm_+AK_H+o) = h0; *(uint32_t*)(asm_+AK_H+o+2) = h1;
        *(uint32_t*)(asm_+AK_L+o) = l0; *(uint32_t*)(asm_+AK_L+o+2) = l1;
        split2(vv.x,vv.y,h0,l0); split2(vv.z,vv.w,h1,l1);
        *(uint32_t*)(asm_+AV_H+o) = h0; *(uint32_t*)(asm_+AV_H+o+2) = h1;
        *(uint32_t*)(asm_+AV_L+o) = l0; *(uint32_t*)(asm_+AV_L+o+2) = l1;
      }
    }
    __syncthreads();

    // S = Q @ K^T  (m16 x n64, k=64)
    float s[8][4];
    #pragma unroll
    for(int nb=0;nb<8;nb++)
      #pragma unroll
      for(int q=0;q<4;q++) s[nb][q]=0.f;
    #pragma unroll
    for(int ks=0;ks<4;ks++){
      uint32_t kb0[8], kb1[8], klo0[8], klo1[8];
      #pragma unroll
      for(int pr=0;pr<4;pr++){
        int n = pr*16 + ((mi>>1)<<3) + wi;
        uint32_t off = (uint32_t)(n*ASROW + ks*16 + ((mi&1)<<3))*2;
        uint32_t r0,r1,r2,r3;
        ldsm4(r0,r1,r2,r3, smemBase + AK_H*2 + off);
        kb0[2*pr]=r0; kb1[2*pr]=r1; kb0[2*pr+1]=r2; kb1[2*pr+1]=r3;
        ldsm4(r0,r1,r2,r3, smemBase + AK_L*2 + off);
        klo0[2*pr]=r0; klo1[2*pr]=r1; klo0[2*pr+1]=r2; klo1[2*pr+1]=r3;
      }
      #pragma unroll
      for(int nb=0;nb<8;nb++){
        mma16816(s[nb], qh[ks][0],qh[ks][1],qh[ks][2],qh[ks][3], kb0[nb],kb1[nb]);
        mma16816(s[nb], qh[ks][0],qh[ks][1],qh[ks][2],qh[ks][3], klo0[nb],klo1[nb]);
        mma16816(s[nb], ql[ks][0],ql[ks][1],ql[ks][2],ql[ks][3], kb0[nb],kb1[nb]);
      }
    }

    // online softmax per row-half
    float p[8][4];
    #pragma unroll
    for(int hr=0;hr<2;hr++){
      float mloc = -1e30f;
      #pragma unroll
      for(int nb=0;nb<8;nb++){
        float a = s[nb][hr*2+0]*0.125f, bb = s[nb][hr*2+1]*0.125f;
        s[nb][hr*2+0]=a; s[nb][hr*2+1]=bb;
        mloc = fmaxf(mloc, fmaxf(a,bb));
      }
      mloc = fmaxf(mloc, __shfl_xor_sync(0xffffffffu, mloc, 1));
      mloc = fmaxf(mloc, __shfl_xor_sync(0xffffffffu, mloc, 2));
      float m_new = fmaxf(m_st[hr], mloc);
      float corr = __expf(m_st[hr]-m_new);
      float lloc = 0.f;
      #pragma unroll
      for(int nb=0;nb<8;nb++){
        float p0 = __expf(s[nb][hr*2+0]-m_new);
        float p1 = __expf(s[nb][hr*2+1]-m_new);
        p[nb][hr*2+0]=p0; p[nb][hr*2+1]=p1;
        lloc += p0+p1;
      }
      lloc += __shfl_xor_sync(0xffffffffu, lloc, 1);
      lloc += __shfl_xor_sync(0xffffffffu, lloc, 2);
      l_st[hr] = l_st[hr]*corr + lloc;
      m_st[hr] = m_new;
      #pragma unroll
      for(int nb=0;nb<8;nb++){ o_acc[nb][hr*2+0]*=corr; o_acc[nb][hr*2+1]*=corr; }
    }

    // O += P @ V  (A = P frags, B = V via ldmatrix.trans)
    #pragma unroll
    for(int ks=0;ks<4;ks++){
      uint32_t pa0,pa1,pa2,pa3, pl0,pl1,pl2,pl3;
      split2(p[2*ks][0],   p[2*ks][1],   pa0, pl0);
      split2(p[2*ks][2],   p[2*ks][3],   pa1, pl1);
      split2(p[2*ks+1][0], p[2*ks+1][1], pa2, pl2);
      split2(p[2*ks+1][2], p[2*ks+1][3], pa3, pl3);
      #pragma unroll
      for(int pr=0;pr<4;pr++){
        int key = ks*16 + ((mi&1)<<3) + wi;
        int d0  = pr*16 + ((mi>>1)<<3);
        uint32_t off = (uint32_t)(key*ASROW + d0)*2;
        uint32_t vh0,vh1,vh2,vh3, vl0,vl1,vl2,vl3;
        ldsm4t(vh0,vh1,vh2,vh3, smemBase + AV_H*2 + off);
        ldsm4t(vl0,vl1,vl2,vl3, smemBase + AV_L*2 + off);
        mma16816(o_acc[2*pr],   pa0,pa1,pa2,pa3, vh0,vh1);
        mma16816(o_acc[2*pr],   pa0,pa1,pa2,pa3, vl0,vl1);
        mma16816(o_acc[2*pr],   pl0,pl1,pl2,pl3, vh0,vh1);
        mma16816(o_acc[2*pr+1], pa0,pa1,pa2,pa3, vh2,vh3);
        mma16816(o_acc[2*pr+1], pa0,pa1,pa2,pa3, vl2,vl3);
        mma16816(o_acc[2*pr+1], pl0,pl1,pl2,pl3, vh2,vh3);
      }
    }
  }

  // epilogue
  #pragma unroll
  for(int hr=0;hr<2;hr++){
    float inv = 1.f/l_st[hr];
    int row = q0 + wid*16 + hr*8 + g8;
    #pragma unroll
    for(int nb=0;nb<8;nb++){
      int col = h*64 + nb*8 + tg*2;
      float2 ov; ov.x = o_acc[nb][hr*2+0]*inv; ov.y = o_acc[nb][hr*2+1]*inv;
      *(float2*)(g_attn + ((size_t)(b*1024+row))*DIM + col) = ov;
    }
  }
}

// ---------------- elementwise node ops (warp-per-row) ----------------
__global__ void post_elt(int c, const float* __restrict__ node_g, const float* __restrict__ node_beta){
  int act = g_node_act[c];
  if(act==0||act==1||act==3) return;
  float aw = g_node_aw[c];
  int wid = threadIdx.x>>5, lane = threadIdx.x&31;
  int row = blockIdx.x*8 + wid;
  size_t off=(size_t)row*DIM;
  const float* q=g_qkv[0]+off; const float* k=g_qkv[1]+off; const float* v=g_qkv[2]+off;
  float* o = g_outbuf[c]+off;
  if(act==4||act==5||act==6){
    #pragma unroll
    for(int j=0;j<4;j++){
      int col = lane*4 + j*128;
      float4 qv = *(const float4*)(q+col);
      float4 ov;
      if(act==4){
        float4 kv = *(const float4*)(k+col);
        float4 vv = *(const float4*)(v+col);
        ov.x=aw*(qv.x*sigmoidf(kv.x)+vv.x); ov.y=aw*(qv.y*sigmoidf(kv.y)+vv.y);
        ov.z=aw*(qv.z*sigmoidf(kv.z)+vv.z); ov.w=aw*(qv.w*sigmoidf(kv.w)+vv.w);
      } else if(act==5){
        float4 tv = *(const float4*)(g_tt[0]+off+col);
        ov.x=aw*(qv.x+tv.x); ov.y=aw*(qv.y+tv.y); ov.z=aw*(qv.z+tv.z); ov.w=aw*(qv.w+tv.w);
      } else {
        float4 kv = *(const float4*)(k+col);
        ov.x=aw*(qv.x+kv.x); ov.y=aw*(qv.y+kv.y); ov.z=aw*(qv.z+kv.z); ov.w=aw*(qv.w+kv.w);
      }
      *(float4*)(o+col)=ov;
    }
    return;
  }
  // act 2: LN(q+k+v); act 7: LN(q)
  float4 x[4];
  #pragma unroll
  for(int j=0;j<4;j++){
    int col = lane*4 + j*128;
    float4 qv = *(const float4*)(q+col);
    if(act==2){
      float4 kv = *(const float4*)(k+col);
      float4 vv = *(const float4*)(v+col);
      qv.x+=kv.x+vv.x; qv.y+=kv.y+vv.y; qv.z+=kv.z+vv.z; qv.w+=kv.w+vv.w;
    }
    x[j]=qv;
  }
  float s=0.f;
  #pragma unroll
  for(int j=0;j<4;j++) s += x[j].x+x[j].y+x[j].z+x[j].w;
  float mean = warpReduceSum(s)*(1.f/512.f);
  float s2=0.f;
  #pragma unroll
  for(int j=0;j<4;j++){
    float a=x[j].x-mean,b=x[j].y-mean,cc=x[j].z-mean,dd=x[j].w-mean;
    s2 += a*a+b*b+cc*cc+dd*dd;
  }
  float rstd = rsqrtf(warpReduceSum(s2)*(1.f/512.f)+1e-6f);
  const float* g  = node_g    + (size_t)c*DIM;
  const float* be = node_beta + (size_t)c*DIM;
  #pragma unroll
  for(int j=0;j<4;j++){
    int col = lane*4 + j*128;
    float4 gv = *(const float4*)(g+col);
    float4 bv = *(const float4*)(be+col);
    float4 ov;
    ov.x=aw*((x[j].x-mean)*rstd*gv.x+bv.x); ov.y=aw*((x[j].y-mean)*rstd*gv.y+bv.y);
    ov.z=aw*((x[j].z-mean)*rstd*gv.z+bv.z); ov.w=aw*((x[j].w-mean)*rstd*gv.w+bv.w);
    *(float4*)(o+col)=ov;
  }
}

// ---------------- final: sum remaining nodes + LN (warp-per-row) ----------------
__global__ void final_kernel(const float* __restrict__ og, const float* __restrict__ obe, float* __restrict__ out){
  int wid = threadIdx.x>>5, lane = threadIdx.x&31;
  int row = blockIdx.x*8 + wid;
  int mask = g_rem_mask;
  size_t off=(size_t)row*DIM;
  float4 x[4];
  #pragma unroll
  for(int j=0;j<4;j++){ x[j].x=0;x[j].y=0;x[j].z=0;x[j].w=0; }
  #pragma unroll
  for(int i=0;i<8;i++) if((mask>>i)&1){
    #pragma unroll
    for(int j=0;j<4;j++){
      float4 v = *(const float4*)(g_outbuf[i]+off+lane*4+j*128);
      x[j].x+=v.x; x[j].y+=v.y; x[j].z+=v.z; x[j].w+=v.w;
    }
  }
  float s=0.f;
  #pragma unroll
  for(int j=0;j<4;j++) s += x[j].x+x[j].y+x[j].z+x[j].w;
  float mean = warpReduceSum(s)*(1.f/512.f);
  float s2=0.f;
  #pragma unroll
  for(int j=0;j<4;j++){
    float a=x[j].x-mean,b=x[j].y-mean,cc=x[j].z-mean,dd=x[j].w-mean;
    s2 += a*a+b*b+cc*cc+dd*dd;
  }
  float rstd = rsqrtf(warpReduceSum(s2)*(1.f/512.f)+1e-6f);
  #pragma unroll
  for(int j=0;j<4;j++){
    int col = lane*4 + j*128;
    float4 gv = *(const float4*)(og+col);
    float4 bv = *(const float4*)(obe+col);
    float4 ov;
    ov.x=(x[j].x-mean)*rstd*gv.x+bv.x; ov.y=(x[j].y-mean)*rstd*gv.y+bv.y;
    ov.z=(x[j].z-mean)*rstd*gv.z+bv.z; ov.w=(x[j].w-mean)*rstd*gv.w+bv.w;
    *(float4*)(out+off+col)=ov;
  }
}

extern "C" void kernel_launch(void* const* d_in, const int* in_sizes, int n_in,
                              void* d_out, int out_size) {
  (void)in_sizes; (void)n_in; (void)out_size;
  const float* inpute    = (const float*)d_in[0];
  const float* inputo    = (const float*)d_in[1];
  const float* node_p    = (const float*)d_in[2];
  const float* edge_p    = (const float*)d_in[3];
  const float* edge_W    = (const float*)d_in[4];
  const float* edge_b    = (const float*)d_in[5];
  const float* edge_g    = (const float*)d_in[6];
  const float* edge_beta = (const float*)d_in[7];
  const float* node_W    = (const float*)d_in[8];
  const float* node_b    = (const float*)d_in[9];
  const float* node_g    = (const float*)d_in[10];
  const float* node_beta = (const float*)d_in[11];
  const float* out_g     = (const float*)d_in[12];
  const float* out_beta  = (const float*)d_in[13];
  float* out = (float*)d_out;

  const int gemmSmem = 8*BUFE*(int)sizeof(__nv_bfloat16); // 81920 bytes
  cudaFuncSetAttribute(gemm_kernel, cudaFuncAttributeMaxDynamicSharedMemorySize, gemmSmem);
  const int attnSmem = ATTN_SMEM_ELEMS*(int)sizeof(__nv_bfloat16); // 73728 bytes
  cudaFuncSetAttribute(attn_kernel, cudaFuncAttributeMaxDynamicSharedMemorySize, attnSmem);

  route_kernel<<<1,1>>>(node_p, edge_p);
  convw_kernel<<<dim3(16,16,66),256>>>(edge_W, node_W);
  for(int c=0;c<8;c++){
    prep_kernel<<<dim3(512,1,3),256>>>(c, inpute, inputo, edge_g, edge_beta);
    gemm_kernel<<<dim3(4,32,3),256,gemmSmem>>>(c,0,inpute,inputo,edge_b,node_b);
    lnq_kernel<<<512,256>>>(c, node_g, node_beta);
    gemm_kernel<<<dim3(4,32,3),256,gemmSmem>>>(c,3,inpute,inputo,edge_b,node_b);
    attn_kernel<<<dim3(8,32),256,attnSmem>>>(c);
    gemm_kernel<<<dim3(4,32,1),256,gemmSmem>>>(c,6,inpute,inputo,edge_b,node_b);
    post_elt<<<512,256>>>(c, node_g, node_beta);
  }
  final_kernel<<<512,256>>>(out_g, out_beta, out);
}